// round 4
// baseline (speedup 1.0000x reference)
#include <cuda_runtime.h>
#include <math.h>

// ---------------------------------------------------------------------------
// QuantumNATHybrid: pooled-feature quadratic-form collapse.
//
//   feats[b,k] = mean over x[b,0, 0:6, 6k:6k+6]          (only 672B prefix/img)
//   qout[b,w]  = (s^T A_w s) / (s^T s),  s = raw block sums (scale-invariant:
//                the /36 pooling mean and the /||.|| normalization both cancel)
//   A_w        = Re(M^H diag(Z_w) M) restricted to cols 0..3, M = circuit(qweights)
//   h = relu(qout @ w1 + b1); out = h @ w2 + b2; batchnorm over B with gamma/beta
//
// Kernels:  qsim (A_w from qweights) -> main (per-image) -> stats -> norm
// ---------------------------------------------------------------------------

__device__ float g_A[64];                 // [w][j][k]
__device__ float g_partials[8192 * 8];    // per-block: 4 sums + 4 sumsq
__device__ float g_mu[4];
__device__ float g_rstd[4];

__device__ __forceinline__ float cz_sign(int i) {
    int b0 = (i >> 3) & 1, b1 = (i >> 2) & 1, b2 = (i >> 1) & 1, b3 = i & 1;
    int s = (b0 & b1) + (b1 & b2) + (b2 & b3) + (b3 & b0);
    return (s & 1) ? -1.0f : 1.0f;
}

// ---- Kernel A: simulate circuit on 4 basis columns, build A_w (64 threads) ----
__global__ void qsim_kernel(const float* __restrict__ qw) {
    __shared__ float sr[4][16], si[4][16];
    int tid = threadIdx.x;

    if (tid < 32) {
        int j = tid >> 3;   // column (initial basis state index 0..3)
        int p = tid & 7;    // pair id 0..7

        // init: column j = e_j
        int ia = 2 * p, ib = 2 * p + 1;
        sr[j][ia] = (ia == j) ? 1.0f : 0.0f;  si[j][ia] = 0.0f;
        sr[j][ib] = (ib == j) ? 1.0f : 0.0f;  si[j][ib] = 0.0f;
        __syncwarp();

        for (int l = 0; l < 2; l++) {
            for (int w = 0; w < 4; w++) {
                int R  = 1 << (3 - w);
                int i0 = ((p & ~(R - 1)) << 1) | (p & (R - 1));
                int i1 = i0 | R;

                float r0 = sr[j][i0], m0 = si[j][i0];
                float r1 = sr[j][i1], m1 = si[j][i1];
                const float* a = qw + (l * 4 + w) * 3;
                float c, s, nr0, ni0, nr1, ni1;

                // RX(tx): [[c, -is],[-is, c]]
                sincosf(0.5f * a[0], &s, &c);
                nr0 = c * r0 + s * m1;   ni0 = c * m0 - s * r1;
                nr1 = s * m0 + c * r1;   ni1 = -s * r0 + c * m1;
                r0 = nr0; m0 = ni0; r1 = nr1; m1 = ni1;

                // RY(ty): [[c, -s],[s, c]]
                sincosf(0.5f * a[1], &s, &c);
                nr0 = c * r0 - s * r1;   ni0 = c * m0 - s * m1;
                nr1 = s * r0 + c * r1;   ni1 = s * m0 + c * m1;
                r0 = nr0; m0 = ni0; r1 = nr1; m1 = ni1;

                // RZ(tz): diag(c - is, c + is)
                sincosf(0.5f * a[2], &s, &c);
                nr0 = c * r0 + s * m0;   ni0 = c * m0 - s * r0;
                nr1 = c * r1 - s * m1;   ni1 = c * m1 + s * r1;
                r0 = nr0; m0 = ni0; r1 = nr1; m1 = ni1;

                if (w == 3) {            // CZ ring: pairs (0,1)(1,2)(2,3)(3,0)
                    float s0 = cz_sign(i0), s1 = cz_sign(i1);
                    r0 *= s0; m0 *= s0; r1 *= s1; m1 *= s1;
                }

                sr[j][i0] = r0; si[j][i0] = m0;
                sr[j][i1] = r1; si[j][i1] = m1;
                __syncwarp();
            }
        }
    }
    __syncthreads();

    // A_w[j][k] = sum_i Z(i,w) * (Mr[i][j]*Mr[i][k] + Mi[i][j]*Mi[i][k])
    int w = tid >> 4, j = (tid >> 2) & 3, k = tid & 3;
    float acc = 0.0f;
#pragma unroll
    for (int i = 0; i < 16; i++) {
        float z = 1.0f - 2.0f * (float)((i >> (3 - w)) & 1);
        acc += z * (sr[j][i] * sr[k][i] + si[j][i] * si[k][i]);
    }
    g_A[tid] = acc;
}

// ---- Kernel B: warp-per-image: pool -> quadratic form -> MLP -> raw out ----
__global__ void __launch_bounds__(256) main_kernel(
    const float* __restrict__ x,
    const float* __restrict__ w1, const float* __restrict__ b1,
    const float* __restrict__ w2, const float* __restrict__ b2,
    float* __restrict__ out, int Bn)
{
    __shared__ float sA[64];
    __shared__ float s_out[8][4];

    // Stage A_w into shared; overlap with the pooling loads (sync is below).
    if (threadIdx.x < 64) sA[threadIdx.x] = g_A[threadIdx.x];

    int lane = threadIdx.x & 31;
    int wrp  = threadIdx.x >> 5;
    int img  = blockIdx.x * 8 + wrp;
    bool valid = (img < Bn);

    // ---- pooling: 42 contiguous float4 = image prefix rows 0..5 ----
    float a0 = 0.f, a1 = 0.f, a2 = 0.f, a3 = 0.f;
    if (valid) {
        const float4* p = (const float4*)(x + (size_t)img * 784);
#pragma unroll
        for (int it = 0; it < 2; it++) {
            int t = lane + it * 32;
            if (t < 42) {
                float4 v = p[t];
                float f[4] = { v.x, v.y, v.z, v.w };
#pragma unroll
                for (int e = 0; e < 4; e++) {
                    int idx = 4 * t + e;
                    int col = idx - (idx / 28) * 28;
                    if (col < 24) {
                        if      (col <  6) a0 += f[e];
                        else if (col < 12) a1 += f[e];
                        else if (col < 18) a2 += f[e];
                        else               a3 += f[e];
                    }
                }
            }
        }
    }
#pragma unroll
    for (int off = 16; off; off >>= 1) {
        a0 += __shfl_xor_sync(0xffffffffu, a0, off);
        a1 += __shfl_xor_sync(0xffffffffu, a1, off);
        a2 += __shfl_xor_sync(0xffffffffu, a2, off);
        a3 += __shfl_xor_sync(0xffffffffu, a3, off);
    }

    __syncthreads();   // sA ready (hidden under the pooling loads above)

    // ---- quantum output: qout[w] = (s^T A_w s) / (s^T s) ----
    float sv[4] = { a0, a1, a2, a3 };
    float ss  = a0 * a0 + a1 * a1 + a2 * a2 + a3 * a3;
    float inv = 1.0f / ss;
    float q[4];
#pragma unroll
    for (int w = 0; w < 4; w++) {
        float acc = 0.f;
#pragma unroll
        for (int jj = 0; jj < 4; jj++)
#pragma unroll
            for (int kk = 0; kk < 4; kk++)
                acc += sA[w * 16 + jj * 4 + kk] * sv[jj] * sv[kk];
        q[w] = acc * inv;
    }

    // ---- MLP: lane owns hidden units lane, lane+32 ----
    float h0 = b1[lane], h1 = b1[lane + 32];
#pragma unroll
    for (int k = 0; k < 4; k++) {
        h0 += q[k] * w1[k * 64 + lane];
        h1 += q[k] * w1[k * 64 + lane + 32];
    }
    h0 = fmaxf(h0, 0.f);
    h1 = fmaxf(h1, 0.f);

    float o[4];
#pragma unroll
    for (int c = 0; c < 4; c++)
        o[c] = h0 * w2[lane * 4 + c] + h1 * w2[(lane + 32) * 4 + c];
#pragma unroll
    for (int off = 16; off; off >>= 1) {
#pragma unroll
        for (int c = 0; c < 4; c++)
            o[c] += __shfl_xor_sync(0xffffffffu, o[c], off);
    }

    if (lane == 0) {
        if (valid) {
            float4 res = make_float4(o[0] + b2[0], o[1] + b2[1],
                                     o[2] + b2[2], o[3] + b2[3]);
            ((float4*)out)[img] = res;
            s_out[wrp][0] = res.x; s_out[wrp][1] = res.y;
            s_out[wrp][2] = res.z; s_out[wrp][3] = res.w;
        } else {
            s_out[wrp][0] = 0.f; s_out[wrp][1] = 0.f;
            s_out[wrp][2] = 0.f; s_out[wrp][3] = 0.f;
        }
    }
    __syncthreads();

    // per-block partials: [sum(c=0..3), sumsq(c=0..3)]  (deterministic order)
    if (threadIdx.x < 8) {
        int c = threadIdx.x & 3, half = threadIdx.x >> 2;
        float acc = 0.f;
#pragma unroll
        for (int wi = 0; wi < 8; wi++) {
            float v = s_out[wi][c];
            acc += half ? v * v : v;
        }
        g_partials[blockIdx.x * 8 + half * 4 + c] = acc;
    }
}

// ---- Kernel C: reduce block partials -> mu, rstd (1 block, doubles) ----
__global__ void stats_kernel(int nblk, int Bn) {
    __shared__ double red[256];
    int t = threadIdx.x;
    int c = t & 7, idx = t >> 3;
    double acc = 0.0;
    for (int i = idx; i < nblk; i += 32)
        acc += (double)g_partials[i * 8 + c];
    red[t] = acc;
    __syncthreads();
    for (int off = 128; off >= 8; off >>= 1) {
        if (t < off) red[t] += red[t + off];
        __syncthreads();
    }
    if (t < 4) {
        double mu  = red[t] / (double)Bn;
        double var = red[t + 4] / (double)Bn - mu * mu;
        g_mu[t]   = (float)mu;
        g_rstd[t] = (float)(1.0 / sqrt(var + 1e-5));
    }
}

// ---- Kernel D: in-place batchnorm of d_out ----
__global__ void norm_kernel(float* __restrict__ out,
                            const float* __restrict__ gamma,
                            const float* __restrict__ beta, int Bn) {
    int i = blockIdx.x * blockDim.x + threadIdx.x;
    if (i < Bn) {
        float4 v = ((float4*)out)[i];
        v.x = (v.x - g_mu[0]) * g_rstd[0] * gamma[0] + beta[0];
        v.y = (v.y - g_mu[1]) * g_rstd[1] * gamma[1] + beta[1];
        v.z = (v.z - g_mu[2]) * g_rstd[2] * gamma[2] + beta[2];
        v.w = (v.w - g_mu[3]) * g_rstd[3] * gamma[3] + beta[3];
        ((float4*)out)[i] = v;
    }
}

extern "C" void kernel_launch(void* const* d_in, const int* in_sizes, int n_in,
                              void* d_out, int out_size) {
    const float* x     = (const float*)d_in[0];
    const float* qw    = (const float*)d_in[1];
    const float* w1    = (const float*)d_in[2];
    const float* b1    = (const float*)d_in[3];
    const float* w2    = (const float*)d_in[4];
    const float* b2    = (const float*)d_in[5];
    const float* gamma = (const float*)d_in[6];
    const float* beta  = (const float*)d_in[7];
    float* out = (float*)d_out;

    int Bn   = in_sizes[0] / 784;           // 32768
    int nblk = (Bn + 7) / 8;                // 4096 (fits g_partials: 8192 max)
    if (nblk > 8192) nblk = 8192;           // safety: scratch bound

    qsim_kernel<<<1, 64>>>(qw);
    main_kernel<<<nblk, 256>>>(x, w1, b1, w2, b2, out, Bn);
    stats_kernel<<<1, 256>>>(nblk, Bn);
    norm_kernel<<<(Bn + 255) / 256, 256>>>(out, gamma, beta, Bn);
}

// round 5
// speedup vs baseline: 1.7771x; 1.7771x over previous
#include <cuda_runtime.h>
#include <math.h>

// ---------------------------------------------------------------------------
// QuantumNATHybrid — fully fused single persistent kernel.
//
//   feats[b,k] = mean over x[b,0, 0:6, 6k:6k+6]   (672B contiguous prefix/img)
//   qout[b,w]  = (s^T A_w s) / (s^T s)   (pool-mean and L2-norm cancel)
//   A_w        = Re(M^H diag(Z_w) M)|cols 0..3,  M = 2-layer circuit(qweights)
//   h = relu(qout@w1+b1); out = h@w2+b2; batchnorm over B.
//
// Phases inside ONE kernel: circuit-sim (per block) -> per-image loop ->
// block partials -> software grid barrier (last block computes stats in
// doubles) -> in-place normalize.  Deterministic: all FP sums fixed-order.
// ---------------------------------------------------------------------------

__device__ float g_partials[1024 * 8];    // per-block: 4 sums + 4 sumsq
__device__ float g_mu[4];
__device__ float g_rstd[4];
__device__ unsigned int g_arrive = 0;     // reset to 0 by last block each launch
__device__ unsigned int g_release = 0;    // monotonically increasing generation

__device__ __forceinline__ float cz_sign(int i) {
    int b0 = (i >> 3) & 1, b1 = (i >> 2) & 1, b2 = (i >> 1) & 1, b3 = i & 1;
    int s = (b0 & b1) + (b1 & b2) + (b2 & b3) + (b3 & b0);
    return (s & 1) ? -1.0f : 1.0f;
}

__global__ void __launch_bounds__(256) fused_kernel(
    const float* __restrict__ x,
    const float* __restrict__ qw,
    const float* __restrict__ w1, const float* __restrict__ b1,
    const float* __restrict__ w2, const float* __restrict__ b2,
    const float* __restrict__ gamma, const float* __restrict__ beta,
    float* __restrict__ out, int Bn)
{
    __shared__ float sr[4][16], si[4][16];
    __shared__ float sA[64];
    __shared__ float s_wacc[8][8];
    __shared__ double red[256];
    __shared__ unsigned s_islast, s_gen;

    int tid  = threadIdx.x;
    int lane = tid & 31;
    int wrp  = tid >> 5;

    // ===== Phase 0: circuit sim (warp 0) -> A_w (threads 0..63) =====
    if (tid < 32) {
        int j = tid >> 3;   // basis column 0..3
        int p = tid & 7;    // amplitude pair 0..7
        int ia = 2 * p, ib = 2 * p + 1;
        sr[j][ia] = (ia == j) ? 1.0f : 0.0f;  si[j][ia] = 0.0f;
        sr[j][ib] = (ib == j) ? 1.0f : 0.0f;  si[j][ib] = 0.0f;
        __syncwarp();

        for (int l = 0; l < 2; l++) {
            for (int w = 0; w < 4; w++) {
                int R  = 1 << (3 - w);
                int i0 = ((p & ~(R - 1)) << 1) | (p & (R - 1));
                int i1 = i0 | R;

                float r0 = sr[j][i0], m0 = si[j][i0];
                float r1 = sr[j][i1], m1 = si[j][i1];
                const float* a = qw + (l * 4 + w) * 3;
                float c, s, nr0, ni0, nr1, ni1;

                // RX: [[c,-is],[-is,c]]
                sincosf(0.5f * a[0], &s, &c);
                nr0 = c * r0 + s * m1;   ni0 = c * m0 - s * r1;
                nr1 = s * m0 + c * r1;   ni1 = -s * r0 + c * m1;
                r0 = nr0; m0 = ni0; r1 = nr1; m1 = ni1;

                // RY: [[c,-s],[s,c]]
                sincosf(0.5f * a[1], &s, &c);
                nr0 = c * r0 - s * r1;   ni0 = c * m0 - s * m1;
                nr1 = s * r0 + c * r1;   ni1 = s * m0 + c * m1;
                r0 = nr0; m0 = ni0; r1 = nr1; m1 = ni1;

                // RZ: diag(c-is, c+is)
                sincosf(0.5f * a[2], &s, &c);
                nr0 = c * r0 + s * m0;   ni0 = c * m0 - s * r0;
                nr1 = c * r1 - s * m1;   ni1 = c * m1 + s * r1;
                r0 = nr0; m0 = ni0; r1 = nr1; m1 = ni1;

                if (w == 3) {            // CZ ring (0,1)(1,2)(2,3)(3,0)
                    float s0 = cz_sign(i0), s1 = cz_sign(i1);
                    r0 *= s0; m0 *= s0; r1 *= s1; m1 *= s1;
                }
                sr[j][i0] = r0; si[j][i0] = m0;
                sr[j][i1] = r1; si[j][i1] = m1;
                __syncwarp();
            }
        }
    }
    __syncthreads();
    if (tid < 64) {
        int w = tid >> 4, j = (tid >> 2) & 3, k = tid & 3;
        float acc = 0.0f;
#pragma unroll
        for (int i = 0; i < 16; i++) {
            float z = 1.0f - 2.0f * (float)((i >> (3 - w)) & 1);
            acc += z * (sr[j][i] * sr[k][i] + si[j][i] * si[k][i]);
        }
        sA[tid] = acc;
    }
    __syncthreads();

    // ===== Phase 1: persistent warp-per-image loop =====
    float acc_s[4] = {0.f, 0.f, 0.f, 0.f};
    float acc_q[4] = {0.f, 0.f, 0.f, 0.f};

    for (int img = blockIdx.x * 8 + wrp; img < Bn; img += gridDim.x * 8) {
        // pooling: 42 contiguous float4 = rows 0..5 of the image
        float a0 = 0.f, a1 = 0.f, a2 = 0.f, a3 = 0.f;
        const float4* p = (const float4*)(x + (size_t)img * 784);
#pragma unroll
        for (int it = 0; it < 2; it++) {
            int t = lane + it * 32;
            if (t < 42) {
                float4 v = __ldcs(p + t);      // streaming: never re-read
                float f[4] = { v.x, v.y, v.z, v.w };
#pragma unroll
                for (int e = 0; e < 4; e++) {
                    int idx = 4 * t + e;
                    int col = idx - (idx / 28) * 28;
                    if (col < 24) {
                        if      (col <  6) a0 += f[e];
                        else if (col < 12) a1 += f[e];
                        else if (col < 18) a2 += f[e];
                        else               a3 += f[e];
                    }
                }
            }
        }
#pragma unroll
        for (int off = 16; off; off >>= 1) {
            a0 += __shfl_xor_sync(0xffffffffu, a0, off);
            a1 += __shfl_xor_sync(0xffffffffu, a1, off);
            a2 += __shfl_xor_sync(0xffffffffu, a2, off);
            a3 += __shfl_xor_sync(0xffffffffu, a3, off);
        }

        // qout[w] = (s^T A_w s) / (s^T s)
        float sv[4] = { a0, a1, a2, a3 };
        float inv = 1.0f / (a0*a0 + a1*a1 + a2*a2 + a3*a3);
        float q[4];
#pragma unroll
        for (int w = 0; w < 4; w++) {
            float acc = 0.f;
#pragma unroll
            for (int jj = 0; jj < 4; jj++)
#pragma unroll
                for (int kk = 0; kk < 4; kk++)
                    acc += sA[w * 16 + jj * 4 + kk] * sv[jj] * sv[kk];
            q[w] = acc * inv;
        }

        // MLP: lane owns hidden units lane, lane+32
        float h0 = b1[lane], h1 = b1[lane + 32];
#pragma unroll
        for (int k = 0; k < 4; k++) {
            h0 += q[k] * w1[k * 64 + lane];
            h1 += q[k] * w1[k * 64 + lane + 32];
        }
        h0 = fmaxf(h0, 0.f);
        h1 = fmaxf(h1, 0.f);

        float o[4];
#pragma unroll
        for (int c = 0; c < 4; c++)
            o[c] = h0 * w2[lane * 4 + c] + h1 * w2[(lane + 32) * 4 + c];
#pragma unroll
        for (int off = 16; off; off >>= 1) {
#pragma unroll
            for (int c = 0; c < 4; c++)
                o[c] += __shfl_xor_sync(0xffffffffu, o[c], off);
        }
        // all lanes now hold the reduced value (xor butterfly)
        float r0 = o[0] + b2[0], r1 = o[1] + b2[1];
        float r2 = o[2] + b2[2], r3 = o[3] + b2[3];
        if (lane == 0)
            ((float4*)out)[img] = make_float4(r0, r1, r2, r3);

        acc_s[0] += r0;      acc_s[1] += r1;
        acc_s[2] += r2;      acc_s[3] += r3;
        acc_q[0] += r0 * r0; acc_q[1] += r1 * r1;
        acc_q[2] += r2 * r2; acc_q[3] += r3 * r3;
    }

    // ===== Phase 2: block partials (deterministic order) =====
    if (lane == 0) {
#pragma unroll
        for (int c = 0; c < 4; c++) {
            s_wacc[wrp][c]     = acc_s[c];
            s_wacc[wrp][4 + c] = acc_q[c];
        }
    }
    __syncthreads();
    if (tid < 8) {
        float a = 0.f;
#pragma unroll
        for (int wi = 0; wi < 8; wi++) a += s_wacc[wi][tid];
        g_partials[blockIdx.x * 8 + tid] = a;
    }
    __threadfence();   // make partials + out visible before arriving

    // ===== Phase 3: software grid barrier; last block computes stats =====
    if (tid == 0) {
        unsigned gen = *(volatile unsigned*)&g_release;  // sample pre-arrive
        unsigned old = atomicAdd(&g_arrive, 1);
        s_islast = (old == gridDim.x - 1) ? 1u : 0u;
        s_gen = gen;
    }
    __syncthreads();

    if (s_islast) {
        int c = tid & 7, idx = tid >> 3;
        double a = 0.0;
        for (int i = idx; i < (int)gridDim.x; i += 32)
            a += (double)__ldcg(&g_partials[i * 8 + c]);
        red[tid] = a;
        __syncthreads();
        for (int off = 128; off >= 8; off >>= 1) {
            if (tid < off) red[tid] += red[tid + off];
            __syncthreads();
        }
        if (tid < 4) {
            double mu  = red[tid] / (double)Bn;
            double var = red[tid + 4] / (double)Bn - mu * mu;
            g_mu[tid]   = (float)mu;
            g_rstd[tid] = (float)(1.0 / sqrt(var + 1e-5));
        }
        __syncthreads();
        if (tid == 0) {
            g_arrive = 0;                 // self-reset for next graph replay
            __threadfence();              // publish stats before release
            atomicAdd(&g_release, 1);
        }
    } else {
        if (tid == 0) {
            while (*(volatile unsigned*)&g_release == s_gen) { }
        }
        __syncthreads();
    }
    __threadfence();

    // ===== Phase 4: in-place batchnorm (grid-stride over images) =====
    float mu[4], rs[4], gm[4], bt[4];
#pragma unroll
    for (int c = 0; c < 4; c++) {
        mu[c] = __ldcg(&g_mu[c]);
        rs[c] = __ldcg(&g_rstd[c]);
        gm[c] = gamma[c];
        bt[c] = beta[c];
    }
    for (int i = blockIdx.x * blockDim.x + tid; i < Bn;
         i += gridDim.x * blockDim.x) {
        float4 v = __ldcg(((const float4*)out) + i);
        v.x = (v.x - mu[0]) * rs[0] * gm[0] + bt[0];
        v.y = (v.y - mu[1]) * rs[1] * gm[1] + bt[1];
        v.z = (v.z - mu[2]) * rs[2] * gm[2] + bt[2];
        v.w = (v.w - mu[3]) * rs[3] * gm[3] + bt[3];
        ((float4*)out)[i] = v;
    }
}

extern "C" void kernel_launch(void* const* d_in, const int* in_sizes, int n_in,
                              void* d_out, int out_size) {
    const float* x     = (const float*)d_in[0];
    const float* qw    = (const float*)d_in[1];
    const float* w1    = (const float*)d_in[2];
    const float* b1    = (const float*)d_in[3];
    const float* w2    = (const float*)d_in[4];
    const float* b2    = (const float*)d_in[5];
    const float* gamma = (const float*)d_in[6];
    const float* beta  = (const float*)d_in[7];
    float* out = (float*)d_out;

    int Bn = in_sizes[0] / 784;             // 32768

    // Grid sizing: must be fully resident for the software barrier.
    // (Host code here runs only during capture, never on replay.)
    int dev = 0, sms = 148, maxB = 1;
    cudaGetDevice(&dev);
    cudaDeviceGetAttribute(&sms, cudaDevAttrMultiProcessorCount, dev);
    cudaOccupancyMaxActiveBlocksPerMultiprocessor(&maxB, fused_kernel, 256, 0);
    if (maxB < 1) maxB = 1;
    if (maxB > 4) maxB = 4;
    int grid = sms * maxB;
    if (grid > 1024) grid = 1024;           // g_partials capacity
    if (grid < 1) grid = 1;

    fused_kernel<<<grid, 256>>>(x, qw, w1, b1, w2, b2, gamma, beta, out, Bn);
}